// round 16
// baseline (speedup 1.0000x reference)
#include <cuda_runtime.h>
#include <cuda_fp16.h>
#include <mma.h>

using namespace nvcuda;

#define N_NODES 100000
#define N_EDGES 3200000
#define CH      128
#define NG      256
#define NC      32
#define APAD    136   // half elements per smem row (128 + 8)

// ---------------- scratch ----------------
__device__ __half g_y16[(size_t)N_NODES * CH]; // (x@W)*dinv[row], fp16
__device__ __half g_h[(size_t)N_NODES * CH];   // layer output, fp16
__device__ float  g_dinv[N_NODES];
__device__ int    g_deg[N_NODES];              // pure in-degree; zeroed by scan_k for next call
__device__ int    g_rowptr[N_NODES + 1];
__device__ int    g_cursor[N_NODES];
__device__ int    g_csrc[N_EDGES];
__device__ float  g_pool[NG * CH];

// ---------------- CSR construction ----------------
// g_deg starts all-zero (zero-init at load; re-zeroed by scan_k each call).
__global__ void hist_k(const int4* __restrict__ dst4) {
    const int n4 = N_EDGES / 4;
    int stride = gridDim.x * blockDim.x;
    int i = blockIdx.x * blockDim.x + threadIdx.x;
    for (; i + 3 * stride < n4; i += 4 * stride) {
        int4 a = dst4[i];
        int4 b = dst4[i + stride];
        int4 c = dst4[i + 2 * stride];
        int4 d = dst4[i + 3 * stride];
        atomicAdd(&g_deg[a.x], 1); atomicAdd(&g_deg[a.y], 1);
        atomicAdd(&g_deg[a.z], 1); atomicAdd(&g_deg[a.w], 1);
        atomicAdd(&g_deg[b.x], 1); atomicAdd(&g_deg[b.y], 1);
        atomicAdd(&g_deg[b.z], 1); atomicAdd(&g_deg[b.w], 1);
        atomicAdd(&g_deg[c.x], 1); atomicAdd(&g_deg[c.y], 1);
        atomicAdd(&g_deg[c.z], 1); atomicAdd(&g_deg[c.w], 1);
        atomicAdd(&g_deg[d.x], 1); atomicAdd(&g_deg[d.y], 1);
        atomicAdd(&g_deg[d.z], 1); atomicAdd(&g_deg[d.w], 1);
    }
    for (; i < n4; i += stride) {
        int4 a = dst4[i];
        atomicAdd(&g_deg[a.x], 1); atomicAdd(&g_deg[a.y], 1);
        atomicAdd(&g_deg[a.z], 1); atomicAdd(&g_deg[a.w], 1);
    }
}

__global__ void scan_k() {
    __shared__ int ssum[1024];
    const int CHUNK = (N_NODES + 1023) / 1024;
    int t  = threadIdx.x;
    int lo = t * CHUNK;
    int hi = min(lo + CHUNK, N_NODES);
    int s = 0;
    for (int v = lo; v < hi; v++) s += g_deg[v];    // in-degree only
    ssum[t] = s;
    __syncthreads();
    for (int off = 1; off < 1024; off <<= 1) {
        int val = (t >= off) ? ssum[t - off] : 0;
        __syncthreads();
        ssum[t] += val;
        __syncthreads();
    }
    int run = (t == 0) ? 0 : ssum[t - 1];
    for (int v = lo; v < hi; v++) {
        int din = g_deg[v];
        g_deg[v] = 0;                                // self-clean for next call
        g_rowptr[v] = run;
        g_cursor[v] = run;
        run += din;
        g_dinv[v] = rsqrtf((float)(din + 1));        // +1 self-loop
    }
    if (t == 1023) g_rowptr[N_NODES] = N_EDGES;
}

__global__ void fill_k(const int4* __restrict__ src4, const int4* __restrict__ dst4) {
    const int n4 = N_EDGES / 4;
    int stride = gridDim.x * blockDim.x;
    int i = blockIdx.x * blockDim.x + threadIdx.x;
    for (; i + 3 * stride < n4; i += 4 * stride) {
        int4 sa = src4[i];
        int4 da = dst4[i];
        int4 sb = src4[i + stride];
        int4 db = dst4[i + stride];
        int4 sc = src4[i + 2 * stride];
        int4 dc = dst4[i + 2 * stride];
        int4 sd = src4[i + 3 * stride];
        int4 dd = dst4[i + 3 * stride];
        int p0  = atomicAdd(&g_cursor[da.x], 1);
        int p1  = atomicAdd(&g_cursor[da.y], 1);
        int p2  = atomicAdd(&g_cursor[da.z], 1);
        int p3  = atomicAdd(&g_cursor[da.w], 1);
        int p4  = atomicAdd(&g_cursor[db.x], 1);
        int p5  = atomicAdd(&g_cursor[db.y], 1);
        int p6  = atomicAdd(&g_cursor[db.z], 1);
        int p7  = atomicAdd(&g_cursor[db.w], 1);
        int p8  = atomicAdd(&g_cursor[dc.x], 1);
        int p9  = atomicAdd(&g_cursor[dc.y], 1);
        int p10 = atomicAdd(&g_cursor[dc.z], 1);
        int p11 = atomicAdd(&g_cursor[dc.w], 1);
        int p12 = atomicAdd(&g_cursor[dd.x], 1);
        int p13 = atomicAdd(&g_cursor[dd.y], 1);
        int p14 = atomicAdd(&g_cursor[dd.z], 1);
        int p15 = atomicAdd(&g_cursor[dd.w], 1);
        g_csrc[p0]  = sa.x; g_csrc[p1]  = sa.y; g_csrc[p2]  = sa.z; g_csrc[p3]  = sa.w;
        g_csrc[p4]  = sb.x; g_csrc[p5]  = sb.y; g_csrc[p6]  = sb.z; g_csrc[p7]  = sb.w;
        g_csrc[p8]  = sc.x; g_csrc[p9]  = sc.y; g_csrc[p10] = sc.z; g_csrc[p11] = sc.w;
        g_csrc[p12] = sd.x; g_csrc[p13] = sd.y; g_csrc[p14] = sd.z; g_csrc[p15] = sd.w;
    }
    for (; i < n4; i += stride) {
        int4 s = src4[i];
        int4 d = dst4[i];
        int p0 = atomicAdd(&g_cursor[d.x], 1);
        int p1 = atomicAdd(&g_cursor[d.y], 1);
        int p2 = atomicAdd(&g_cursor[d.z], 1);
        int p3 = atomicAdd(&g_cursor[d.w], 1);
        g_csrc[p0] = s.x;
        g_csrc[p1] = s.y;
        g_csrc[p2] = s.z;
        g_csrc[p3] = s.w;
    }
}

// ---------------- GEMM (tensor core): g_y16 = half((A @ W) * dinv[row]) ----------------
#define GEMM_SMEM (2 * 128 * APAD * 2)

template <int A_IS_HALF>
__global__ void __launch_bounds__(256) gemm_wmma_k(
    const float* __restrict__ Af, const float* __restrict__ W, int M)
{
    extern __shared__ char smraw[];
    __half* As = (__half*)smraw;                         // [128][APAD], A[m][k]
    __half* Bs = (__half*)(smraw + 128 * APAD * 2);      // [128][APAD], B[k][n] = W
    float*  Cs = (float*)smraw;                          // [128][128] staging (reused)

    int tid = threadIdx.x;

    for (int i = tid; i < 128 * 32; i += 256) {
        int k = i >> 5, c4 = i & 31;
        float4 v = *(const float4*)&W[k * 128 + c4 * 4];
        __half2 h0 = __floats2half2_rn(v.x, v.y);
        __half2 h1 = __floats2half2_rn(v.z, v.w);
        *(uint2*)&Bs[k * APAD + c4 * 4] = make_uint2(*(unsigned*)&h0, *(unsigned*)&h1);
    }

    int row0 = blockIdx.x * 128;
    if (A_IS_HALF) {
        const __half* Ah = g_h;
        for (int i = tid; i < 128 * 16; i += 256) {
            int r = i >> 4, c8 = i & 15;
            uint4 v = make_uint4(0u, 0u, 0u, 0u);
            if (row0 + r < M) v = *(const uint4*)&Ah[(size_t)(row0 + r) * CH + c8 * 8];
            *(uint4*)&As[r * APAD + c8 * 8] = v;
        }
    } else {
        for (int i = tid; i < 128 * 32; i += 256) {
            int r = i >> 5, c4 = i & 31;
            float4 v = make_float4(0.f, 0.f, 0.f, 0.f);
            if (row0 + r < M) v = *(const float4*)&Af[(size_t)(row0 + r) * CH + c4 * 4];
            __half2 h0 = __floats2half2_rn(v.x, v.y);
            __half2 h1 = __floats2half2_rn(v.z, v.w);
            *(uint2*)&As[r * APAD + c4 * 4] = make_uint2(*(unsigned*)&h0, *(unsigned*)&h1);
        }
    }
    __syncthreads();

    int wid = tid >> 5;
    int wm = wid >> 2, wn = wid & 3;
    int wrow = wm * 64, wcol = wn * 32;

    wmma::fragment<wmma::accumulator, 16, 16, 16, float> c[4][2];
    #pragma unroll
    for (int i = 0; i < 4; i++)
        #pragma unroll
        for (int j = 0; j < 2; j++) wmma::fill_fragment(c[i][j], 0.f);

    #pragma unroll
    for (int kk = 0; kk < 128; kk += 16) {
        wmma::fragment<wmma::matrix_a, 16, 16, 16, __half, wmma::row_major> a[4];
        wmma::fragment<wmma::matrix_b, 16, 16, 16, __half, wmma::row_major> b[2];
        #pragma unroll
        for (int i = 0; i < 4; i++)
            wmma::load_matrix_sync(a[i], As + (wrow + i * 16) * APAD + kk, APAD);
        #pragma unroll
        for (int j = 0; j < 2; j++)
            wmma::load_matrix_sync(b[j], Bs + kk * APAD + wcol + j * 16, APAD);
        #pragma unroll
        for (int i = 0; i < 4; i++)
            #pragma unroll
            for (int j = 0; j < 2; j++)
                wmma::mma_sync(c[i][j], a[i], b[j], c[i][j]);
    }

    __syncthreads();
    #pragma unroll
    for (int i = 0; i < 4; i++)
        #pragma unroll
        for (int j = 0; j < 2; j++)
            wmma::store_matrix_sync(Cs + (wrow + i * 16) * 128 + wcol + j * 16,
                                    c[i][j], 128, wmma::mem_row_major);
    __syncthreads();

    for (int i = tid; i < 128 * 16; i += 256) {
        int r = i >> 4, c8 = i & 15;
        int gr = row0 + r;
        if (gr < M) {
            float dv = g_dinv[gr];
            const float* s = &Cs[r * 128 + c8 * 8];
            __half2 p0 = __floats2half2_rn(s[0] * dv, s[1] * dv);
            __half2 p1 = __floats2half2_rn(s[2] * dv, s[3] * dv);
            __half2 p2 = __floats2half2_rn(s[4] * dv, s[5] * dv);
            __half2 p3 = __floats2half2_rn(s[6] * dv, s[7] * dv);
            *(uint4*)&g_y16[(size_t)gr * CH + c8 * 8] =
                make_uint4(*(unsigned*)&p0, *(unsigned*)&p1,
                           *(unsigned*)&p2, *(unsigned*)&p3);
        }
    }
}

// ---------------- aggregation (R13 form, frozen): warp/node, uint2/lane, HADD2 ----------------
__device__ __forceinline__ void acc4(float4& a, uint2 u) {
    float2 f0 = __half22float2(*(__half2*)&u.x);
    float2 f1 = __half22float2(*(__half2*)&u.y);
    a.x += f0.x; a.y += f0.y; a.z += f1.x; a.w += f1.y;
}

__global__ void __launch_bounds__(256) aggregate_k(const float* __restrict__ bias) {
    int w = (blockIdx.x * blockDim.x + threadIdx.x) >> 5;
    if (w >= N_NODES) return;
    int lane = threadIdx.x & 31;

    const uint2* y2 = (const uint2*)g_y16;

    float4 a0 = make_float4(0.f, 0.f, 0.f, 0.f);
    acc4(a0, y2[(size_t)w * 32 + lane]);     // self-loop (fp32)

    const __half2 hz = __float2half2_rn(0.f);
    int beg = g_rowptr[w], end = g_rowptr[w + 1];
    int i = beg;
    for (; i + 32 <= end; i += 32) {
        int idx = g_csrc[i + lane];
        __half2 hA0 = hz, hA1 = hz, hB0 = hz, hB1 = hz;  // 2 edge-parity chains (<=16 adds each)
        #pragma unroll
        for (int j = 0; j < 32; j += 2) {
            int s0 = __shfl_sync(0xffffffffu, idx, j);
            int s1 = __shfl_sync(0xffffffffu, idx, j + 1);
            uint2 u0 = y2[(size_t)s0 * 32 + lane];
            uint2 u1 = y2[(size_t)s1 * 32 + lane];
            hA0 = __hadd2(hA0, *(__half2*)&u0.x);
            hA1 = __hadd2(hA1, *(__half2*)&u0.y);
            hB0 = __hadd2(hB0, *(__half2*)&u1.x);
            hB1 = __hadd2(hB1, *(__half2*)&u1.y);
        }
        float2 f;
        f = __half22float2(hA0); a0.x += f.x; a0.y += f.y;
        f = __half22float2(hB0); a0.x += f.x; a0.y += f.y;
        f = __half22float2(hA1); a0.z += f.x; a0.w += f.y;
        f = __half22float2(hB1); a0.z += f.x; a0.w += f.y;
    }
    if (i < end) {
        int cnt = end - i;
        int idx = g_csrc[min(i + lane, end - 1)];
        __half2 h0 = hz, h1 = hz;
        for (int j = 0; j < cnt; j++) {
            int s = __shfl_sync(0xffffffffu, idx, j);
            uint2 u = y2[(size_t)s * 32 + lane];
            h0 = __hadd2(h0, *(__half2*)&u.x);
            h1 = __hadd2(h1, *(__half2*)&u.y);
            if ((j & 7) == 7) {                      // flush every 8 to bound chains
                float2 f = __half22float2(h0); a0.x += f.x; a0.y += f.y;
                f = __half22float2(h1); a0.z += f.x; a0.w += f.y;
                h0 = hz; h1 = hz;
            }
        }
        float2 f = __half22float2(h0); a0.x += f.x; a0.y += f.y;
        f = __half22float2(h1); a0.z += f.x; a0.w += f.y;
    }

    float dv = g_dinv[w];
    float4 b = ((const float4*)bias)[lane];
    float rx = fmaxf(fmaf(a0.x, dv, b.x), 0.f);
    float ry = fmaxf(fmaf(a0.y, dv, b.y), 0.f);
    float rz = fmaxf(fmaf(a0.z, dv, b.z), 0.f);
    float rw = fmaxf(fmaf(a0.w, dv, b.w), 0.f);
    __half2 h0 = __floats2half2_rn(rx, ry);
    __half2 h1 = __floats2half2_rn(rz, rw);
    ((uint2*)g_h)[(size_t)w * 32 + lane] =
        make_uint2(*(unsigned*)&h0, *(unsigned*)&h1);
}

// ---------------- pooling + FC ----------------
__device__ __forceinline__ int lower_bound_i(const int* a, int n, int key) {
    int lo = 0, hi = n;
    while (lo < hi) { int mid = (lo + hi) >> 1; if (a[mid] < key) lo = mid + 1; else hi = mid; }
    return lo;
}

// 8 row-lanes x 32 lanes; each lane owns 4 channels (uint2), full 256B coalesced rows.
__global__ void __launch_bounds__(256) pool_k(const int* __restrict__ batch) {
    __shared__ float4 sred[8][32];
    __shared__ int slo, shi;
    int g = blockIdx.x;
    if (threadIdx.x == 0) {
        slo = lower_bound_i(batch, N_NODES, g);
        shi = lower_bound_i(batch, N_NODES, g + 1);
    }
    __syncthreads();
    int lo = slo, hi = shi;
    int l = threadIdx.x & 31;
    int r = threadIdx.x >> 5;
    const uint2* h2 = (const uint2*)g_h;
    float4 a = make_float4(0.f, 0.f, 0.f, 0.f);
    for (int row = lo + r; row < hi; row += 8)
        acc4(a, h2[(size_t)row * 32 + l]);
    sred[r][l] = a;
    __syncthreads();
    if (r == 0) {
        #pragma unroll
        for (int k = 1; k < 8; k++) {
            float4 b = sred[k][l];
            a.x += b.x; a.y += b.y; a.z += b.z; a.w += b.w;
        }
        float cnt = fmaxf((float)(hi - lo), 1.0f);
        ((float4*)g_pool)[g * 32 + l] =
            make_float4(a.x / cnt, a.y / cnt, a.z / cnt, a.w / cnt);
    }
}

__global__ void fc_k(const float* __restrict__ Wfc, const float* __restrict__ bfc,
                     float* __restrict__ out) {
    int g = blockIdx.x;
    int c = threadIdx.x;
    float acc = bfc[c];
    #pragma unroll 4
    for (int k = 0; k < CH; k++)
        acc = fmaf(g_pool[g * CH + k], Wfc[k * NC + c], acc);
    out[g * NC + c] = acc;
}

// ---------------- launcher ----------------
extern "C" void kernel_launch(void* const* d_in, const int* in_sizes, int n_in,
                              void* d_out, int out_size) {
    const float* x     = (const float*)d_in[0];
    const int*   ei    = (const int*)  d_in[1];
    const int*   batch = (const int*)  d_in[2];
    const float* W1    = (const float*)d_in[3];
    const float* b1    = (const float*)d_in[4];
    const float* W2    = (const float*)d_in[5];
    const float* b2    = (const float*)d_in[6];
    const float* Wfc   = (const float*)d_in[7];
    const float* bfc   = (const float*)d_in[8];
    float* out = (float*)d_out;

    const int4* src4 = (const int4*)ei;
    const int4* dst4 = (const int4*)(ei + N_EDGES);

    static cudaStream_t s2 = nullptr;
    static cudaEvent_t  e0 = nullptr, e1 = nullptr;
    if (!s2) {
        cudaStreamCreate(&s2);
        cudaEventCreateWithFlags(&e0, cudaEventDisableTiming);
        cudaEventCreateWithFlags(&e1, cudaEventDisableTiming);
        cudaFuncSetAttribute(gemm_wmma_k<0>,
                             cudaFuncAttributeMaxDynamicSharedMemorySize, GEMM_SMEM);
        cudaFuncSetAttribute(gemm_wmma_k<1>,
                             cudaFuncAttributeMaxDynamicSharedMemorySize, GEMM_SMEM);
    }

    int gemm_blocks = (N_NODES + 127) / 128;
    int agg_blocks  = (N_NODES * 32 + 255) / 256;

    // serial prefix: hist (on zeroed g_deg) + scan (self-cleans g_deg)
    hist_k<<<800, 256>>>(dst4);
    scan_k<<<1, 1024>>>();

    // fork: fill_k on s2 concurrent with gemm1 (needs only dinv)
    cudaEventRecord(e0, 0);
    cudaStreamWaitEvent(s2, e0, 0);
    fill_k<<<800, 256, 0, s2>>>(src4, dst4);
    gemm_wmma_k<0><<<gemm_blocks, 256, GEMM_SMEM>>>(x, W1, N_NODES);
    cudaEventRecord(e1, s2);
    cudaStreamWaitEvent(0, e1, 0);

    // layer 1 aggregate
    aggregate_k<<<agg_blocks, 256>>>(b1);
    // layer 2
    gemm_wmma_k<1><<<gemm_blocks, 256, GEMM_SMEM>>>(nullptr, W2, N_NODES);
    aggregate_k<<<agg_blocks, 256>>>(b2);
    // pool + fc
    pool_k<<<NG, 256>>>(batch);
    fc_k<<<NG, NC>>>(Wfc, bfc, out);
}

// round 17
// speedup vs baseline: 1.1068x; 1.1068x over previous
#include <cuda_runtime.h>
#include <cuda_fp16.h>
#include <mma.h>

using namespace nvcuda;

#define N_NODES 100000
#define N_EDGES 3200000
#define CH      128
#define NG      256
#define NC      32
#define APAD    136   // half elements per smem row (128 + 8)

// ---------------- scratch ----------------
__device__ __half g_y16[(size_t)N_NODES * CH]; // (x@W)*dinv[row], fp16
__device__ __half g_h[(size_t)N_NODES * CH];   // layer output, fp16
__device__ float  g_dinv[N_NODES];
__device__ int    g_deg[N_NODES];
__device__ int    g_rowptr[N_NODES + 1];
__device__ int    g_cursor[N_NODES];
__device__ int    g_csrc[N_EDGES];
__device__ float  g_pool[NG * CH];

// ---------------- CSR construction (R15 form) ----------------
__global__ void init_deg_k() {
    int v = blockIdx.x * blockDim.x + threadIdx.x;
    if (v < N_NODES) g_deg[v] = 1;   // self-loop
}

__global__ void hist_k(const int4* __restrict__ dst4) {
    int stride = gridDim.x * blockDim.x;
    int i = blockIdx.x * blockDim.x + threadIdx.x;
    for (; i + stride < N_EDGES / 4; i += 2 * stride) {
        int4 d0 = dst4[i];
        int4 d1 = dst4[i + stride];
        atomicAdd(&g_deg[d0.x], 1);
        atomicAdd(&g_deg[d0.y], 1);
        atomicAdd(&g_deg[d0.z], 1);
        atomicAdd(&g_deg[d0.w], 1);
        atomicAdd(&g_deg[d1.x], 1);
        atomicAdd(&g_deg[d1.y], 1);
        atomicAdd(&g_deg[d1.z], 1);
        atomicAdd(&g_deg[d1.w], 1);
    }
    if (i < N_EDGES / 4) {
        int4 d = dst4[i];
        atomicAdd(&g_deg[d.x], 1);
        atomicAdd(&g_deg[d.y], 1);
        atomicAdd(&g_deg[d.z], 1);
        atomicAdd(&g_deg[d.w], 1);
    }
}

__global__ void scan_k() {
    __shared__ int ssum[1024];
    const int CHUNK = (N_NODES + 1023) / 1024;
    int t  = threadIdx.x;
    int lo = t * CHUNK;
    int hi = min(lo + CHUNK, N_NODES);
    int s = 0;
    for (int v = lo; v < hi; v++) s += g_deg[v] - 1;
    ssum[t] = s;
    __syncthreads();
    for (int off = 1; off < 1024; off <<= 1) {
        int val = (t >= off) ? ssum[t - off] : 0;
        __syncthreads();
        ssum[t] += val;
        __syncthreads();
    }
    int run = (t == 0) ? 0 : ssum[t - 1];
    for (int v = lo; v < hi; v++) {
        g_rowptr[v] = run;
        g_cursor[v] = run;
        int d = g_deg[v];
        run += d - 1;
        g_dinv[v] = rsqrtf((float)d);
    }
    if (t == 1023) g_rowptr[N_NODES] = N_EDGES;
}

__global__ void fill_k(const int4* __restrict__ src4, const int4* __restrict__ dst4) {
    int stride = gridDim.x * blockDim.x;
    int i = blockIdx.x * blockDim.x + threadIdx.x;
    for (; i + stride < N_EDGES / 4; i += 2 * stride) {
        int4 s0 = src4[i];
        int4 d0 = dst4[i];
        int4 s1 = src4[i + stride];
        int4 d1 = dst4[i + stride];
        int p0 = atomicAdd(&g_cursor[d0.x], 1);
        int p1 = atomicAdd(&g_cursor[d0.y], 1);
        int p2 = atomicAdd(&g_cursor[d0.z], 1);
        int p3 = atomicAdd(&g_cursor[d0.w], 1);
        int p4 = atomicAdd(&g_cursor[d1.x], 1);
        int p5 = atomicAdd(&g_cursor[d1.y], 1);
        int p6 = atomicAdd(&g_cursor[d1.z], 1);
        int p7 = atomicAdd(&g_cursor[d1.w], 1);
        g_csrc[p0] = s0.x;
        g_csrc[p1] = s0.y;
        g_csrc[p2] = s0.z;
        g_csrc[p3] = s0.w;
        g_csrc[p4] = s1.x;
        g_csrc[p5] = s1.y;
        g_csrc[p6] = s1.z;
        g_csrc[p7] = s1.w;
    }
    if (i < N_EDGES / 4) {
        int4 s = src4[i];
        int4 d = dst4[i];
        int p0 = atomicAdd(&g_cursor[d.x], 1);
        int p1 = atomicAdd(&g_cursor[d.y], 1);
        int p2 = atomicAdd(&g_cursor[d.z], 1);
        int p3 = atomicAdd(&g_cursor[d.w], 1);
        g_csrc[p0] = s.x;
        g_csrc[p1] = s.y;
        g_csrc[p2] = s.z;
        g_csrc[p3] = s.w;
    }
}

// ---------------- GEMM (tensor core): 64x128 tile, 4 CTAs/SM ----------------
// smem: As[64][APAD] + Bs[128][APAD] fp16 = 52.2 KB; Cs[64][128] f32 reuses As/Bs.
#define GEMM_SMEM ((64 + 128) * APAD * 2)

template <int A_IS_HALF>
__global__ void __launch_bounds__(256) gemm_wmma_k(
    const float* __restrict__ Af, const float* __restrict__ W, int M)
{
    extern __shared__ char smraw[];
    __half* As = (__half*)smraw;                        // [64][APAD], A[m][k]
    __half* Bs = (__half*)(smraw + 64 * APAD * 2);      // [128][APAD], B[k][n] = W
    float*  Cs = (float*)smraw;                         // [64][128] staging (reused)

    int tid = threadIdx.x;

    // W -> Bs straight copy+convert (no transpose)
    for (int i = tid; i < 128 * 32; i += 256) {
        int k = i >> 5, c4 = i & 31;
        float4 v = *(const float4*)&W[k * 128 + c4 * 4];
        __half2 h0 = __floats2half2_rn(v.x, v.y);
        __half2 h1 = __floats2half2_rn(v.z, v.w);
        *(uint2*)&Bs[k * APAD + c4 * 4] = make_uint2(*(unsigned*)&h0, *(unsigned*)&h1);
    }

    int row0 = blockIdx.x * 64;
    if (A_IS_HALF) {
        const __half* Ah = g_h;
        for (int i = tid; i < 64 * 16; i += 256) {
            int r = i >> 4, c8 = i & 15;
            uint4 v = make_uint4(0u, 0u, 0u, 0u);
            if (row0 + r < M) v = *(const uint4*)&Ah[(size_t)(row0 + r) * CH + c8 * 8];
            *(uint4*)&As[r * APAD + c8 * 8] = v;
        }
    } else {
        for (int i = tid; i < 64 * 32; i += 256) {
            int r = i >> 5, c4 = i & 31;
            float4 v = make_float4(0.f, 0.f, 0.f, 0.f);
            if (row0 + r < M) v = *(const float4*)&Af[(size_t)(row0 + r) * CH + c4 * 4];
            __half2 h0 = __floats2half2_rn(v.x, v.y);
            __half2 h1 = __floats2half2_rn(v.z, v.w);
            *(uint2*)&As[r * APAD + c4 * 4] = make_uint2(*(unsigned*)&h0, *(unsigned*)&h1);
        }
    }
    __syncthreads();

    int wid = tid >> 5;
    int wm = wid >> 2, wn = wid & 3;        // 2 x 4 warp grid
    int wrow = wm * 32, wcol = wn * 32;     // 32x32 warp tile

    wmma::fragment<wmma::accumulator, 16, 16, 16, float> c[2][2];
    #pragma unroll
    for (int i = 0; i < 2; i++)
        #pragma unroll
        for (int j = 0; j < 2; j++) wmma::fill_fragment(c[i][j], 0.f);

    #pragma unroll
    for (int kk = 0; kk < 128; kk += 16) {
        wmma::fragment<wmma::matrix_a, 16, 16, 16, __half, wmma::row_major> a[2];
        wmma::fragment<wmma::matrix_b, 16, 16, 16, __half, wmma::row_major> b[2];
        #pragma unroll
        for (int i = 0; i < 2; i++)
            wmma::load_matrix_sync(a[i], As + (wrow + i * 16) * APAD + kk, APAD);
        #pragma unroll
        for (int j = 0; j < 2; j++)
            wmma::load_matrix_sync(b[j], Bs + kk * APAD + wcol + j * 16, APAD);
        #pragma unroll
        for (int i = 0; i < 2; i++)
            #pragma unroll
            for (int j = 0; j < 2; j++)
                wmma::mma_sync(c[i][j], a[i], b[j], c[i][j]);
    }

    __syncthreads();
    #pragma unroll
    for (int i = 0; i < 2; i++)
        #pragma unroll
        for (int j = 0; j < 2; j++)
            wmma::store_matrix_sync(Cs + (wrow + i * 16) * 128 + wcol + j * 16,
                                    c[i][j], 128, wmma::mem_row_major);
    __syncthreads();

    for (int i = tid; i < 64 * 16; i += 256) {
        int r = i >> 4, c8 = i & 15;
        int gr = row0 + r;
        if (gr < M) {
            float dv = g_dinv[gr];
            const float* s = &Cs[r * 128 + c8 * 8];
            __half2 p0 = __floats2half2_rn(s[0] * dv, s[1] * dv);
            __half2 p1 = __floats2half2_rn(s[2] * dv, s[3] * dv);
            __half2 p2 = __floats2half2_rn(s[4] * dv, s[5] * dv);
            __half2 p3 = __floats2half2_rn(s[6] * dv, s[7] * dv);
            *(uint4*)&g_y16[(size_t)gr * CH + c8 * 8] =
                make_uint4(*(unsigned*)&p0, *(unsigned*)&p1,
                           *(unsigned*)&p2, *(unsigned*)&p3);
        }
    }
}

// ---------------- aggregation (R13 form, frozen): warp/node, uint2/lane, HADD2 ----------------
__device__ __forceinline__ void acc4(float4& a, uint2 u) {
    float2 f0 = __half22float2(*(__half2*)&u.x);
    float2 f1 = __half22float2(*(__half2*)&u.y);
    a.x += f0.x; a.y += f0.y; a.z += f1.x; a.w += f1.y;
}

__global__ void __launch_bounds__(256) aggregate_k(const float* __restrict__ bias) {
    int w = (blockIdx.x * blockDim.x + threadIdx.x) >> 5;
    if (w >= N_NODES) return;
    int lane = threadIdx.x & 31;

    const uint2* y2 = (const uint2*)g_y16;

    float4 a0 = make_float4(0.f, 0.f, 0.f, 0.f);
    acc4(a0, y2[(size_t)w * 32 + lane]);     // self-loop (fp32)

    const __half2 hz = __float2half2_rn(0.f);
    int beg = g_rowptr[w], end = g_rowptr[w + 1];
    int i = beg;
    for (; i + 32 <= end; i += 32) {
        int idx = g_csrc[i + lane];
        __half2 hA0 = hz, hA1 = hz, hB0 = hz, hB1 = hz;
        #pragma unroll
        for (int j = 0; j < 32; j += 2) {
            int s0 = __shfl_sync(0xffffffffu, idx, j);
            int s1 = __shfl_sync(0xffffffffu, idx, j + 1);
            uint2 u0 = y2[(size_t)s0 * 32 + lane];
            uint2 u1 = y2[(size_t)s1 * 32 + lane];
            hA0 = __hadd2(hA0, *(__half2*)&u0.x);
            hA1 = __hadd2(hA1, *(__half2*)&u0.y);
            hB0 = __hadd2(hB0, *(__half2*)&u1.x);
            hB1 = __hadd2(hB1, *(__half2*)&u1.y);
        }
        float2 f;
        f = __half22float2(hA0); a0.x += f.x; a0.y += f.y;
        f = __half22float2(hB0); a0.x += f.x; a0.y += f.y;
        f = __half22float2(hA1); a0.z += f.x; a0.w += f.y;
        f = __half22float2(hB1); a0.z += f.x; a0.w += f.y;
    }
    if (i < end) {
        int cnt = end - i;
        int idx = g_csrc[min(i + lane, end - 1)];
        __half2 h0 = hz, h1 = hz;
        for (int j = 0; j < cnt; j++) {
            int s = __shfl_sync(0xffffffffu, idx, j);
            uint2 u = y2[(size_t)s * 32 + lane];
            h0 = __hadd2(h0, *(__half2*)&u.x);
            h1 = __hadd2(h1, *(__half2*)&u.y);
            if ((j & 7) == 7) {
                float2 f = __half22float2(h0); a0.x += f.x; a0.y += f.y;
                f = __half22float2(h1); a0.z += f.x; a0.w += f.y;
                h0 = hz; h1 = hz;
            }
        }
        float2 f = __half22float2(h0); a0.x += f.x; a0.y += f.y;
        f = __half22float2(h1); a0.z += f.x; a0.w += f.y;
    }

    float dv = g_dinv[w];
    float4 b = ((const float4*)bias)[lane];
    float rx = fmaxf(fmaf(a0.x, dv, b.x), 0.f);
    float ry = fmaxf(fmaf(a0.y, dv, b.y), 0.f);
    float rz = fmaxf(fmaf(a0.z, dv, b.z), 0.f);
    float rw = fmaxf(fmaf(a0.w, dv, b.w), 0.f);
    __half2 h0 = __floats2half2_rn(rx, ry);
    __half2 h1 = __floats2half2_rn(rz, rw);
    ((uint2*)g_h)[(size_t)w * 32 + lane] =
        make_uint2(*(unsigned*)&h0, *(unsigned*)&h1);
}

// ---------------- pooling + FC (R15 form) ----------------
__device__ __forceinline__ int lower_bound_i(const int* a, int n, int key) {
    int lo = 0, hi = n;
    while (lo < hi) { int mid = (lo + hi) >> 1; if (a[mid] < key) lo = mid + 1; else hi = mid; }
    return lo;
}

__global__ void pool_k(const int* __restrict__ batch) {
    int g = blockIdx.x;
    __shared__ int slo, shi;
    if (threadIdx.x == 0) {
        slo = lower_bound_i(batch, N_NODES, g);
        shi = lower_bound_i(batch, N_NODES, g + 1);
    }
    __syncthreads();
    int lo = slo, hi = shi;
    int c = threadIdx.x;
    float s = 0.f;
    for (int r = lo; r < hi; r++) s += __half2float(g_h[(size_t)r * CH + c]);
    float cnt = (float)(hi - lo);
    g_pool[g * CH + c] = s / fmaxf(cnt, 1.0f);
}

__global__ void fc_k(const float* __restrict__ Wfc, const float* __restrict__ bfc,
                     float* __restrict__ out) {
    int g = blockIdx.x;
    int c = threadIdx.x;
    float acc = bfc[c];
    #pragma unroll 4
    for (int k = 0; k < CH; k++)
        acc = fmaf(g_pool[g * CH + k], Wfc[k * NC + c], acc);
    out[g * NC + c] = acc;
}

// ---------------- launcher (R15 schedule) ----------------
extern "C" void kernel_launch(void* const* d_in, const int* in_sizes, int n_in,
                              void* d_out, int out_size) {
    const float* x     = (const float*)d_in[0];
    const int*   ei    = (const int*)  d_in[1];
    const int*   batch = (const int*)  d_in[2];
    const float* W1    = (const float*)d_in[3];
    const float* b1    = (const float*)d_in[4];
    const float* W2    = (const float*)d_in[5];
    const float* b2    = (const float*)d_in[6];
    const float* Wfc   = (const float*)d_in[7];
    const float* bfc   = (const float*)d_in[8];
    float* out = (float*)d_out;

    const int4* src4 = (const int4*)ei;
    const int4* dst4 = (const int4*)(ei + N_EDGES);

    static cudaStream_t s2 = nullptr;
    static cudaEvent_t  e0 = nullptr, e1 = nullptr;
    if (!s2) {
        cudaStreamCreate(&s2);
        cudaEventCreateWithFlags(&e0, cudaEventDisableTiming);
        cudaEventCreateWithFlags(&e1, cudaEventDisableTiming);
        cudaFuncSetAttribute(gemm_wmma_k<0>,
                             cudaFuncAttributeMaxDynamicSharedMemorySize, GEMM_SMEM);
        cudaFuncSetAttribute(gemm_wmma_k<1>,
                             cudaFuncAttributeMaxDynamicSharedMemorySize, GEMM_SMEM);
    }

    int gemm_blocks = (N_NODES + 63) / 64;   // 1563
    int agg_blocks  = (N_NODES * 32 + 255) / 256;

    // serial prefix: deg + scan
    init_deg_k<<<(N_NODES + 255) / 256, 256>>>();
    hist_k<<<1184, 256>>>(dst4);
    scan_k<<<1, 1024>>>();

    // fork: fill_k on s2 concurrent with gemm1 (needs only dinv)
    cudaEventRecord(e0, 0);
    cudaStreamWaitEvent(s2, e0, 0);
    fill_k<<<1184, 256, 0, s2>>>(src4, dst4);
    gemm_wmma_k<0><<<gemm_blocks, 256, GEMM_SMEM>>>(x, W1, N_NODES);
    cudaEventRecord(e1, s2);
    cudaStreamWaitEvent(0, e1, 0);

    // layer 1 aggregate
    aggregate_k<<<agg_blocks, 256>>>(b1);
    // layer 2
    gemm_wmma_k<1><<<gemm_blocks, 256, GEMM_SMEM>>>(nullptr, W2, N_NODES);
    aggregate_k<<<agg_blocks, 256>>>(b2);
    // pool + fc
    pool_k<<<NG, 128>>>(batch);
    fc_k<<<NG, NC>>>(Wfc, bfc, out);
}